// round 3
// baseline (speedup 1.0000x reference)
#include <cuda_runtime.h>
#include <cstdint>

// Problem constants
#define M_ROWS   32
#define IN_F     8192
#define OUT_F    32768
#define KWORDS   (IN_F / 2)    // 4096 int32 words per output row (1 useful byte each)
#define AEB      (IN_F / 2)    // 4096 bytes per row in each of the even/odd planes
#define AEW      (AEB / 4)     // 1024 int32 words per row per plane

// ---------------------------------------------------------------------------
// Scratch (no cudaMalloc allowed): quantized activations split into
// even-k and odd-k planes, plus per-row sums for the -8 bias correction.
// ---------------------------------------------------------------------------
__device__ int g_ae[M_ROWS * AEW];      // int8 bytes: ae[m][t] = q(x[m][2t])
__device__ int g_ao[M_ROWS * AEW];      // int8 bytes: ao[m][t] = q(x[m][2t+1])
__device__ int g_rowsum[M_ROWS];        // sum over k of q(x[m][k])

// ---------------------------------------------------------------------------
// Prologue: static int8 quantization of x (round-half-even, clamp +-127),
// packed into even/odd planes, with a block reduction for the row sum.
// One block per row.
// ---------------------------------------------------------------------------
__global__ __launch_bounds__(512) void quant_acts_kernel(
    const float* __restrict__ x, const float* __restrict__ act_scale)
{
    const int m   = blockIdx.x;
    const int tid = threadIdx.x;
    const float s = *act_scale;
    const float* xr = x + (size_t)m * IN_F;

    signed char* ae = reinterpret_cast<signed char*>(g_ae) + m * AEB;
    signed char* ao = reinterpret_cast<signed char*>(g_ao) + m * AEB;

    int lsum = 0;
    for (int t = tid; t < AEB; t += 512) {
        // IEEE-correct division so rounding matches the reference even
        // under --use_fast_math.
        float a0 = __fdiv_rn(xr[2 * t],     s);
        float a1 = __fdiv_rn(xr[2 * t + 1], s);
        float r0 = fminf(fmaxf(rintf(a0), -127.0f), 127.0f);
        float r1 = fminf(fmaxf(rintf(a1), -127.0f), 127.0f);
        int q0 = (int)r0;
        int q1 = (int)r1;
        ae[t] = (signed char)q0;
        ao[t] = (signed char)q1;
        lsum += q0 + q1;
    }

    __shared__ int red[512];
    red[tid] = lsum;
    __syncthreads();
    #pragma unroll
    for (int off = 256; off > 0; off >>= 1) {
        if (tid < off) red[tid] += red[tid + off];
        __syncthreads();
    }
    if (tid == 0) g_rowsum[m] = red[0];
}

// ---------------------------------------------------------------------------
// Main GEMM: each warp owns (8 rows x 4 output channels), lanes split K.
//   - lane l streams weight words [4l .. 4l+3] + 128*i as one uint4 (coalesced
//     512B/warp per channel per iter), __ldcs to avoid polluting L2.
//   - 3x PRMT compacts the 4 useful low bytes into one word; nibbles are
//     sign-handled by (nib ^ 8) with a per-row -8*rowsum correction.
//   - dp4a against register-cached even/odd activation words (reused across
//     the 4 channels -> LSU traffic is 1/4 of the dp4a count).
//   - butterfly shuffle reduction across lanes, fused dequant + bias.
// CTA = 256 threads = 8 warps = 4 row-groups x 2 channel-subgroups
//      -> covers 8 output channels. Grid = OUT_F/8 = 4096 CTAs.
// ---------------------------------------------------------------------------
__global__ __launch_bounds__(256) void int4_gemm_dp4a_kernel(
    const int*   __restrict__ wpacked,   // [OUT_F][KWORDS] int32 (low byte used)
    const float* __restrict__ wscale,    // [OUT_F]
    const float* __restrict__ act_scale, // [1]
    const float* __restrict__ bias,      // [OUT_F]
    float*       __restrict__ out)       // [M_ROWS][OUT_F]
{
    const int tid  = threadIdx.x;
    const int wrp  = tid >> 5;
    const int lane = tid & 31;
    const int rg   = wrp & 3;          // row group: rows rg*8 .. rg*8+7
    const int csub = wrp >> 2;         // 0 or 1
    const int o_base = blockIdx.x * 8 + csub * 4;

    // Per-channel weight pointers (uint4 granularity: 1024 per row)
    const uint4* wq[4];
    #pragma unroll
    for (int c = 0; c < 4; c++)
        wq[c] = reinterpret_cast<const uint4*>(wpacked)
                + (size_t)(o_base + c) * (KWORDS / 4) + lane;

    const int* aeP = g_ae + (rg * 8) * AEW + lane;
    const int* aoP = g_ao + (rg * 8) * AEW + lane;

    int acc[8][4];
    #pragma unroll
    for (int m = 0; m < 8; m++)
        #pragma unroll
        for (int c = 0; c < 4; c++) acc[m][c] = 0;

    #pragma unroll 2
    for (int i = 0; i < 32; i++) {
        // Batch the activation loads first (good MLP, L1-resident).
        int ae[8], ao[8];
        #pragma unroll
        for (int m = 0; m < 8; m++) {
            ae[m] = __ldg(aeP + m * AEW + 32 * i);
            ao[m] = __ldg(aoP + m * AEW + 32 * i);
        }
        #pragma unroll
        for (int c = 0; c < 4; c++) {
            uint4 W = __ldcs(wq[c] + 32 * i);
            // Compact low bytes of 4 words into one dp4a-ready word.
            unsigned u = __byte_perm(W.x, W.y, 0x0040);
            unsigned v = __byte_perm(W.z, W.w, 0x0040);
            unsigned p = __byte_perm(u, v, 0x5410);
            int elo = (int)(( p        & 0x0F0F0F0Fu) ^ 0x08080808u);
            int ehi = (int)(((p >> 4)  & 0x0F0F0F0Fu) ^ 0x08080808u);
            #pragma unroll
            for (int m = 0; m < 8; m++) {
                acc[m][c] = __dp4a(elo, ae[m], acc[m][c]);
                acc[m][c] = __dp4a(ehi, ao[m], acc[m][c]);
            }
        }
    }

    // Warp-level butterfly reduction over the K-split.
    #pragma unroll
    for (int off = 16; off > 0; off >>= 1) {
        #pragma unroll
        for (int m = 0; m < 8; m++)
            #pragma unroll
            for (int c = 0; c < 4; c++)
                acc[m][c] += __shfl_xor_sync(0xffffffffu, acc[m][c], off);
    }

    // Lane (m*4 + c) writes out[row rg*8+m][o_base+c].
    int myacc = 0;
    #pragma unroll
    for (int m = 0; m < 8; m++)
        #pragma unroll
        for (int c = 0; c < 4; c++)
            if (lane == m * 4 + c) myacc = acc[m][c];

    const int mg = rg * 8 + (lane >> 2);
    const int o  = o_base + (lane & 3);
    const float s  = __ldg(act_scale);
    const float rq = (float)myacc - 8.0f * (float)g_rowsum[mg];
    const float y  = rq * (s * __ldg(wscale + o)) + __ldg(bias + o);
    out[(size_t)mg * OUT_F + o] = y;
}

// ---------------------------------------------------------------------------
// Launch: inputs per metadata order:
//   d_in[0] = x             float32 [32, 8192]
//   d_in[1] = weight_packed int32   [32768, 4096]
//   d_in[2] = weight_scale  float32 [32768, 1]
//   d_in[3] = act_scale     float32 [1]
//   d_in[4] = bias          float32 [32768]
// out = float32 [32, 32768]
// ---------------------------------------------------------------------------
extern "C" void kernel_launch(void* const* d_in, const int* in_sizes, int n_in,
                              void* d_out, int out_size)
{
    const float* x  = (const float*)d_in[0];
    const int*   wp = (const int*)  d_in[1];
    const float* ws = (const float*)d_in[2];
    const float* as = (const float*)d_in[3];
    const float* b  = (const float*)d_in[4];
    float* out      = (float*)d_out;

    quant_acts_kernel<<<M_ROWS, 512>>>(x, as);
    int4_gemm_dp4a_kernel<<<OUT_F / 8, 256>>>(wp, ws, as, b, out);
}

// round 4
// speedup vs baseline: 1.7667x; 1.7667x over previous
#include <cuda_runtime.h>
#include <cstdint>

// Problem constants
#define M_ROWS 32
#define IN_F   8192
#define OUT_F  32768
#define NKC    256           // k-chunks of 32
// weight_packed: [OUT_F][4096] int32, each word's LOW BYTE = two int4 nibbles
//   byte t of channel o covers k=2t (low nibble), k=2t+1 (high nibble)

// ---------------------------------------------------------------------------
// Scratch: activations pre-quantized into m16n8k32 A-fragment order.
// g_afrag[(kc*2 + h)*32 + lane] = uint4{a0,a1,a2,a3} for m-tile h (rows 16h..)
//   reg i: row = 16h + (lane>>2) + 8*(i&1), k = 32kc + (lane&3)*4 + 16*(i>>1),
//   bytes little-endian ascending k.
// ---------------------------------------------------------------------------
__device__ uint4 g_afrag[NKC * 2 * 32];   // 256 KB
__device__ int   g_rowsum[M_ROWS];

__device__ __forceinline__ int quant1(float v, float s) {
    // IEEE divide + round-half-even + clamp, matching the reference exactly.
    float r = fminf(fmaxf(rintf(__fdiv_rn(v, s)), -127.0f), 127.0f);
    return (int)r;
}

// 64 blocks x 256 threads = 16384 threads, one uint4 fragment each.
__global__ __launch_bounds__(256) void quant_frag_kernel(
    const float* __restrict__ x, const float* __restrict__ act_scale)
{
    const int t    = blockIdx.x * 256 + threadIdx.x;   // 0..16383
    const float s  = *act_scale;
    const int lane = t & 31;
    const int h    = (t >> 5) & 1;
    const int kc   = t >> 6;
    const int r0   = 16 * h + (lane >> 2);
    const int kb   = 32 * kc + (lane & 3) * 4;

    unsigned reg[4];
    #pragma unroll
    for (int i = 0; i < 4; i++) {
        const int row = r0 + 8 * (i & 1);
        const int k0  = kb + 16 * (i >> 1);
        const float* xp = x + (size_t)row * IN_F + k0;
        unsigned v = 0;
        #pragma unroll
        for (int j = 0; j < 4; j++) {
            int qi = quant1(xp[j], s);
            v |= ((unsigned)qi & 0xffu) << (8 * j);
        }
        reg[i] = v;
    }
    g_afrag[t] = make_uint4(reg[0], reg[1], reg[2], reg[3]);
}

// Per-row sum of quantized activations (for the -8*rowsum nibble correction).
__global__ __launch_bounds__(256) void rowsum_kernel(
    const float* __restrict__ x, const float* __restrict__ act_scale)
{
    const int m   = blockIdx.x;
    const float s = *act_scale;
    int lsum = 0;
    for (int k = threadIdx.x; k < IN_F; k += 256)
        lsum += quant1(x[(size_t)m * IN_F + k], s);

    __shared__ int red[256];
    red[threadIdx.x] = lsum;
    __syncthreads();
    #pragma unroll
    for (int off = 128; off > 0; off >>= 1) {
        if (threadIdx.x < off) red[threadIdx.x] += red[threadIdx.x + off];
        __syncthreads();
    }
    if (threadIdx.x == 0) g_rowsum[m] = red[0];
}

// Two packed words (low bytes b0,b1) -> B-fragment word [lo0,hi0,lo1,hi1],
// nibbles biased via ^8 so e = w+8 in 0..15 (signed correction in epilogue).
__device__ __forceinline__ unsigned unpack_pair(int2 v) {
    unsigned u  = __byte_perm((unsigned)v.x, (unsigned)v.y, 0x0040);
    unsigned lo =  u       & 0x00000F0Fu;
    unsigned hi = (u >> 4) & 0x00000F0Fu;
    return __byte_perm(lo, hi, 0x5140) ^ 0x08080808u;
}

__device__ __forceinline__ void mma_s8(int* d,
    unsigned a0, unsigned a1, unsigned a2, unsigned a3,
    unsigned b0, unsigned b1)
{
    asm volatile(
        "mma.sync.aligned.m16n8k32.row.col.s32.s8.s8.s32 "
        "{%0,%1,%2,%3}, {%4,%5,%6,%7}, {%8,%9}, {%0,%1,%2,%3};\n"
        : "+r"(d[0]), "+r"(d[1]), "+r"(d[2]), "+r"(d[3])
        : "r"(a0), "r"(a1), "r"(a2), "r"(a3), "r"(b0), "r"(b1));
}

// ---------------------------------------------------------------------------
// Main GEMM: 512 CTAs x 128 threads. Each warp: 16 output channels
// (2 n8-tiles) x all 32 rows (2 m16-tiles), full-K accumulation in s32 regs.
// Per k32 chunk: 4x int2 __ldcs weight loads (64B/channel across the warp,
// fully sectored), 4x unpack, 2x LDG.128 A-fragment (L1/L2-resident, shared
// by every warp on the chip), 4x mma. W and A double-buffered.
// ---------------------------------------------------------------------------
__global__ __launch_bounds__(128) void gemm_imma_kernel(
    const int*   __restrict__ wp,        // [OUT_F][4096]
    const float* __restrict__ wscale,    // [OUT_F]
    const float* __restrict__ act_scale, // [1]
    const float* __restrict__ bias,      // [OUT_F]
    float*       __restrict__ out)       // [M_ROWS][OUT_F]
{
    const int lane = threadIdx.x & 31;
    const int wid  = threadIdx.x >> 5;
    const int gw   = blockIdx.x * 4 + wid;
    const int nb   = gw * 16;           // first of this warp's 16 channels
    const int c    = lane & 3;
    const int qd   = lane >> 2;

    // int2 index j covers packed words {2j, 2j+1}; channel row = 2048 int2.
    // Chunk kc reg0 wants words {16kc+2c, +1} -> int2 8kc + c; reg1 -> +4.
    const int2* wp0 = (const int2*)wp + ((size_t)(nb + qd)     * 2048 + c);
    const int2* wp1 = (const int2*)wp + ((size_t)(nb + 8 + qd) * 2048 + c);
    const uint4* af = g_afrag + lane;

    int acc[2][2][4];
    #pragma unroll
    for (int t = 0; t < 2; t++)
        #pragma unroll
        for (int h = 0; h < 2; h++)
            #pragma unroll
            for (int j = 0; j < 4; j++) acc[t][h][j] = 0;

    int2  w[2][4];
    uint4 A[2][2];
    w[0][0] = __ldcs(wp0);     w[0][1] = __ldcs(wp0 + 4);
    w[0][2] = __ldcs(wp1);     w[0][3] = __ldcs(wp1 + 4);
    A[0][0] = __ldg(af);       A[0][1] = __ldg(af + 32);

    #pragma unroll 2
    for (int kc = 0; kc < NKC; kc++) {
        const int cur = kc & 1, nxt = cur ^ 1;
        if (kc + 1 < NKC) {
            const int o = 8 * (kc + 1);
            w[nxt][0] = __ldcs(wp0 + o);     w[nxt][1] = __ldcs(wp0 + o + 4);
            w[nxt][2] = __ldcs(wp1 + o);     w[nxt][3] = __ldcs(wp1 + o + 4);
            A[nxt][0] = __ldg(af + (kc + 1) * 64);
            A[nxt][1] = __ldg(af + (kc + 1) * 64 + 32);
        }
        const unsigned b00 = unpack_pair(w[cur][0]);
        const unsigned b01 = unpack_pair(w[cur][1]);
        const unsigned b10 = unpack_pair(w[cur][2]);
        const unsigned b11 = unpack_pair(w[cur][3]);
        const uint4 A0 = A[cur][0], A1 = A[cur][1];

        mma_s8(acc[0][0], A0.x, A0.y, A0.z, A0.w, b00, b01);
        mma_s8(acc[0][1], A1.x, A1.y, A1.z, A1.w, b00, b01);
        mma_s8(acc[1][0], A0.x, A0.y, A0.z, A0.w, b10, b11);
        mma_s8(acc[1][1], A1.x, A1.y, A1.z, A1.w, b10, b11);
    }

    // Epilogue: dequant + nibble-bias correction + bias, fused.
    const float s = __ldg(act_scale);
    float rs[4];
    #pragma unroll
    for (int i = 0; i < 4; i++) rs[i] = (float)g_rowsum[qd + 8 * i];

    #pragma unroll
    for (int t = 0; t < 2; t++) {
        const int col0 = nb + 8 * t + 2 * c;
        const float sc0 = s * __ldg(wscale + col0);
        const float sc1 = s * __ldg(wscale + col0 + 1);
        const float bb0 = __ldg(bias + col0);
        const float bb1 = __ldg(bias + col0 + 1);
        #pragma unroll
        for (int h = 0; h < 2; h++) {
            #pragma unroll
            for (int j = 0; j < 4; j++) {
                const int row = 16 * h + 8 * (j >> 1) + qd;
                const float rsum = rs[2 * h + (j >> 1)];
                const float yq = (float)acc[t][h][j] - 8.0f * rsum;
                const float y  = yq * ((j & 1) ? sc1 : sc0) + ((j & 1) ? bb1 : bb0);
                out[(size_t)row * OUT_F + col0 + (j & 1)] = y;
            }
        }
    }
}

// ---------------------------------------------------------------------------
// Inputs (metadata order): x f32[32,8192], weight_packed i32[32768,4096],
// weight_scale f32[32768,1], act_scale f32[1], bias f32[32768].
// out f32[32,32768].
// ---------------------------------------------------------------------------
extern "C" void kernel_launch(void* const* d_in, const int* in_sizes, int n_in,
                              void* d_out, int out_size)
{
    const float* x  = (const float*)d_in[0];
    const int*   wpk= (const int*)  d_in[1];
    const float* ws = (const float*)d_in[2];
    const float* as = (const float*)d_in[3];
    const float* b  = (const float*)d_in[4];
    float* out      = (float*)d_out;

    quant_frag_kernel<<<64, 256>>>(x, as);
    rowsum_kernel<<<M_ROWS, 256>>>(x, as);
    gemm_imma_kernel<<<OUT_F / 64, 128>>>(wpk, ws, as, b, out);
}

// round 7
// speedup vs baseline: 2.3150x; 1.3104x over previous
#include <cuda_runtime.h>
#include <cstdint>

// Problem constants
#define M_ROWS 32
#define IN_F   8192
#define OUT_F  32768
#define NKC    256           // k-chunks of 32
// weight_packed: [OUT_F][4096] int32, low byte of each word = two int4 nibbles
//   byte t of channel o covers k=2t (low nibble), k=2t+1 (high nibble)

// ---------------------------------------------------------------------------
// Scratch: activations pre-quantized into m16n8k32 A-fragment order.
// g_afrag[(kc*2 + h)*32 + lane] = uint4{a0..a3} for m-tile h (rows 16h..16h+15)
//   reg i: row = 16h + (lane>>2) + 8*(i&1), k = 32kc + (lane&3)*4 + 16*(i>>1)
// ---------------------------------------------------------------------------
__device__ uint4 g_afrag[NKC * 2 * 32];   // 256 KB
__device__ int   g_rowsum[M_ROWS];

__device__ __forceinline__ int quant1(float v, float s) {
    // IEEE divide + round-half-even + clamp: matches the reference exactly.
    float r = fminf(fmaxf(rintf(__fdiv_rn(v, s)), -127.0f), 127.0f);
    return (int)r;
}

// Zero the rowsum accumulator (graph replays reuse the device global).
__global__ void zero_rowsum_kernel() {
    if (threadIdx.x < M_ROWS) g_rowsum[threadIdx.x] = 0;
}

// ---------------------------------------------------------------------------
// Prologue: quantize x into A-fragment order (float4 loads) AND accumulate
// per-row sums (dp4a against 0x01010101) via smem + global atomics.
// 64 blocks x 256 threads = 16384 threads, one uint4 fragment each.
// ---------------------------------------------------------------------------
__global__ __launch_bounds__(256) void quant_frag_kernel(
    const float* __restrict__ x, const float* __restrict__ act_scale)
{
    __shared__ int rowpart[M_ROWS];
    if (threadIdx.x < M_ROWS) rowpart[threadIdx.x] = 0;
    __syncthreads();

    const int t    = blockIdx.x * 256 + threadIdx.x;   // 0..16383
    const float s  = *act_scale;
    const int lane = t & 31;
    const int h    = (t >> 5) & 1;
    const int kc   = t >> 6;
    const int r0   = 16 * h + (lane >> 2);
    const int kb   = 32 * kc + (lane & 3) * 4;

    unsigned reg[4];
    #pragma unroll
    for (int i = 0; i < 4; i++) {
        const int row = r0 + 8 * (i & 1);
        const int k0  = kb + 16 * (i >> 1);
        const float4 v4 = __ldg(reinterpret_cast<const float4*>(
                                    x + (size_t)row * IN_F + k0));
        unsigned v = 0;
        v |= ((unsigned)quant1(v4.x, s) & 0xffu);
        v |= ((unsigned)quant1(v4.y, s) & 0xffu) << 8;
        v |= ((unsigned)quant1(v4.z, s) & 0xffu) << 16;
        v |= ((unsigned)quant1(v4.w, s) & 0xffu) << 24;
        reg[i] = v;
    }
    g_afrag[t] = make_uint4(reg[0], reg[1], reg[2], reg[3]);

    // Row-sum contributions: regs 0,2 belong to row r0; regs 1,3 to r0+8.
    const int ones = 0x01010101;
    int s0 = __dp4a((int)reg[0], ones, __dp4a((int)reg[2], ones, 0));
    int s1 = __dp4a((int)reg[1], ones, __dp4a((int)reg[3], ones, 0));
    atomicAdd(&rowpart[r0], s0);
    atomicAdd(&rowpart[r0 + 8], s1);
    __syncthreads();
    if (threadIdx.x < M_ROWS)
        atomicAdd(&g_rowsum[threadIdx.x], rowpart[threadIdx.x]);
}

// Two packed words (low bytes b0,b1) -> B-fragment word [lo0,hi0,lo1,hi1],
// nibbles biased via ^8 so e = w+8 in 0..15 (signed correction in epilogue).
__device__ __forceinline__ unsigned unpack_pair(int2 v) {
    unsigned u  = __byte_perm((unsigned)v.x, (unsigned)v.y, 0x0040);
    unsigned lo =  u       & 0x00000F0Fu;
    unsigned hi = (u >> 4) & 0x00000F0Fu;
    return __byte_perm(lo, hi, 0x5140) ^ 0x08080808u;
}

__device__ __forceinline__ void mma_s8(int* d,
    unsigned a0, unsigned a1, unsigned a2, unsigned a3,
    unsigned b0, unsigned b1)
{
    asm volatile(
        "mma.sync.aligned.m16n8k32.row.col.s32.s8.s8.s32 "
        "{%0,%1,%2,%3}, {%4,%5,%6,%7}, {%8,%9}, {%0,%1,%2,%3};\n"
        : "+r"(d[0]), "+r"(d[1]), "+r"(d[2]), "+r"(d[3])
        : "r"(a0), "r"(a1), "r"(a2), "r"(a3), "r"(b0), "r"(b1));
}

// ---------------------------------------------------------------------------
// Main GEMM, K-split x2: 1024 CTAs x 128 threads (4 warps).
//   warp = (channel group cg = wid>>1) x (k-half kh = wid&1)
//   each warp: 16 channels x all 32 rows x half of K (128 kc = 64 kc-pairs)
// Pair-granularity double buffer: prefetch 12 loads (8x int2 W via __ldcs +
// 4x uint4 A via __ldg, L1-resident) for pair p+1 while running 8 unpacks +
// 8 mmas on pair p -> ~4KB in flight per warp, ~20 warps/SM.
// kh=1 partials land in padded smem; kh=0 reduces and runs the fused
// dequant + (-8*rowsum) correction + bias epilogue.
// ---------------------------------------------------------------------------
__global__ __launch_bounds__(128) void gemm_imma_kernel(
    const int*   __restrict__ wp,        // [OUT_F][4096]
    const float* __restrict__ wscale,    // [OUT_F]
    const float* __restrict__ act_scale, // [1]
    const float* __restrict__ bias,      // [OUT_F]
    float*       __restrict__ out)       // [M_ROWS][OUT_F]
{
    __shared__ int red[2][32][17];       // padded: stride 17 kills conflicts

    const int lane = threadIdx.x & 31;
    const int wid  = threadIdx.x >> 5;
    const int kh   = wid & 1;            // k half: kc in [128*kh, 128*kh+128)
    const int cg   = wid >> 1;           // channel group within CTA
    const int nb   = blockIdx.x * 32 + cg * 16;
    const int c    = lane & 3;
    const int qd   = lane >> 2;

    // int2 index j covers packed words {2j,2j+1}; channel row = 2048 int2.
    const int2* wp0 = reinterpret_cast<const int2*>(wp)
                      + ((size_t)(nb + qd) * 2048 + c + (size_t)kh * 1024);
    const int2* wp1 = wp0 + (size_t)8 * 2048;
    const uint4* af = g_afrag + lane + kh * (128 * 64);

    int acc[2][2][4];
    #pragma unroll
    for (int t = 0; t < 2; t++)
        #pragma unroll
        for (int h = 0; h < 2; h++)
            #pragma unroll
            for (int j = 0; j < 4; j++) acc[t][h][j] = 0;

    int2  w[2][8];
    uint4 A[2][4];

    #define LOAD_PAIR(buf, p) do {                                          \
        const int _o = 16 * (p);                                            \
        w[buf][0] = __ldcs(wp0 + _o);      w[buf][1] = __ldcs(wp0 + _o + 4);\
        w[buf][2] = __ldcs(wp1 + _o);      w[buf][3] = __ldcs(wp1 + _o + 4);\
        w[buf][4] = __ldcs(wp0 + _o + 8);  w[buf][5] = __ldcs(wp0 + _o + 12);\
        w[buf][6] = __ldcs(wp1 + _o + 8);  w[buf][7] = __ldcs(wp1 + _o + 12);\
        const int _a = 128 * (p);                                           \
        A[buf][0] = __ldg(af + _a);        A[buf][1] = __ldg(af + _a + 32); \
        A[buf][2] = __ldg(af + _a + 64);   A[buf][3] = __ldg(af + _a + 96); \
    } while (0)

    LOAD_PAIR(0, 0);

    #pragma unroll 2
    for (int p = 0; p < 64; p++) {
        const int cur = p & 1, nxt = cur ^ 1;
        const int pn = (p + 1 < 64) ? p + 1 : 63;   // last prefetch redundant
        LOAD_PAIR(nxt, pn);

        // kc = 2p
        {
            const unsigned b00 = unpack_pair(w[cur][0]);
            const unsigned b01 = unpack_pair(w[cur][1]);
            const unsigned b10 = unpack_pair(w[cur][2]);
            const unsigned b11 = unpack_pair(w[cur][3]);
            const uint4 A0 = A[cur][0], A1 = A[cur][1];
            mma_s8(acc[0][0], A0.x, A0.y, A0.z, A0.w, b00, b01);
            mma_s8(acc[0][1], A1.x, A1.y, A1.z, A1.w, b00, b01);
            mma_s8(acc[1][0], A0.x, A0.y, A0.z, A0.w, b10, b11);
            mma_s8(acc[1][1], A1.x, A1.y, A1.z, A1.w, b10, b11);
        }
        // kc = 2p+1
        {
            const unsigned b00 = unpack_pair(w[cur][4]);
            const unsigned b01 = unpack_pair(w[cur][5]);
            const unsigned b10 = unpack_pair(w[cur][6]);
            const unsigned b11 = unpack_pair(w[cur][7]);
            const uint4 A0 = A[cur][2], A1 = A[cur][3];
            mma_s8(acc[0][0], A0.x, A0.y, A0.z, A0.w, b00, b01);
            mma_s8(acc[0][1], A1.x, A1.y, A1.z, A1.w, b00, b01);
            mma_s8(acc[1][0], A0.x, A0.y, A0.z, A0.w, b10, b11);
            mma_s8(acc[1][1], A1.x, A1.y, A1.z, A1.w, b10, b11);
        }
    }
    #undef LOAD_PAIR

    // Cross-k-half reduction through shared memory.
    if (kh == 1) {
        #pragma unroll
        for (int t = 0; t < 2; t++)
            #pragma unroll
            for (int h = 0; h < 2; h++)
                #pragma unroll
                for (int j = 0; j < 4; j++)
                    red[cg][lane][t * 8 + h * 4 + j] = acc[t][h][j];
    }
    __syncthreads();
    if (kh == 1) return;

    #pragma unroll
    for (int t = 0; t < 2; t++)
        #pragma unroll
        for (int h = 0; h < 2; h++)
            #pragma unroll
            for (int j = 0; j < 4; j++)
                acc[t][h][j] += red[cg][lane][t * 8 + h * 4 + j];

    // Epilogue: dequant + nibble-bias correction + bias, fused.
    const float s = __ldg(act_scale);
    float rs[4];
    #pragma unroll
    for (int i = 0; i < 4; i++) rs[i] = (float)g_rowsum[qd + 8 * i];

    #pragma unroll
    for (int t = 0; t < 2; t++) {
        const int col0 = nb + 8 * t + 2 * c;
        const float sc0 = s * __ldg(wscale + col0);
        const float sc1 = s * __ldg(wscale + col0 + 1);
        const float bb0 = __ldg(bias + col0);
        const float bb1 = __ldg(bias + col0 + 1);
        #pragma unroll
        for (int h = 0; h < 2; h++) {
            #pragma unroll
            for (int j = 0; j < 4; j++) {
                const int row = 16 * h + 8 * (j >> 1) + qd;
                const float rsum = rs[2 * h + (j >> 1)];
                const float yq = (float)acc[t][h][j] - 8.0f * rsum;
                const float y  = yq * ((j & 1) ? sc1 : sc0) + ((j & 1) ? bb1 : bb0);
                out[(size_t)row * OUT_F + col0 + (j & 1)] = y;
            }
        }
    }
}

// ---------------------------------------------------------------------------
// Inputs (metadata order): x f32[32,8192], weight_packed i32[32768,4096],
// weight_scale f32[32768,1], act_scale f32[1], bias f32[32768].
// out f32[32,32768].
// ---------------------------------------------------------------------------
extern "C" void kernel_launch(void* const* d_in, const int* in_sizes, int n_in,
                              void* d_out, int out_size)
{
    const float* x  = (const float*)d_in[0];
    const int*   wpk= (const int*)  d_in[1];
    const float* ws = (const float*)d_in[2];
    const float* as = (const float*)d_in[3];
    const float* b  = (const float*)d_in[4];
    float* out      = (float*)d_out;

    zero_rowsum_kernel<<<1, 32>>>();
    quant_frag_kernel<<<64, 256>>>(x, as);
    gemm_imma_kernel<<<OUT_F / 32, 128>>>(wpk, ws, as, b, out);
}